// round 14
// baseline (speedup 1.0000x reference)
#include <cuda_runtime.h>
#include <cuda_bf16.h>
#include <cstdint>

#define BB 32
#define TT 512
#define KK 256
#define HALF 128

__device__ float g_pair[BB * 2];   // per-(batch, rank) partial sums of E
__device__ float g_nfin[BB];       // replicated normalizer (rank 0 writes)
__device__ float g_js[BB];         // joint score (rank 0 writes)
__device__ unsigned int g_count;   // zero-init; reset every launch

static __device__ __forceinline__ unsigned int f2bf_rn(float x) {
    unsigned int u = __float_as_uint(x);
    return (u + 0x7FFFu + ((u >> 16) & 1u)) >> 16;
}
static __device__ __forceinline__ unsigned int cvt_bf16(float x) {
    unsigned short h;
    asm("cvt.rn.bf16.f32 %0, %1;" : "=h"(h) : "f"(x));
    return (unsigned int)h;
}

#define HFMA2_BF16(d, a, b, c) \
    asm("fma.rn.bf16x2 %0, %1, %2, %3;" : "=r"(d) : "r"(a), "r"(b), "r"(c))

static __device__ __forceinline__ unsigned smem_u32(const void* p) {
    return (unsigned)__cvta_generic_to_shared(p);
}
static __device__ __forceinline__ unsigned mapa_u32(unsigned a, unsigned r) {
    unsigned d;
    asm("mapa.shared::cluster.u32 %0, %1, %2;" : "=r"(d) : "r"(a), "r"(r));
    return d;
}
static __device__ __forceinline__ unsigned ctarank() {
    unsigned r; asm("mov.u32 %0, %%cluster_ctarank;" : "=r"(r)); return r;
}

#define MBAR_INIT(addr, cnt) \
    asm volatile("mbarrier.init.shared.b64 [%0], %1;" :: "r"(addr), "r"(cnt) : "memory")
#define MBAR_EXPECT_TX(addr, bytes) \
    asm volatile("mbarrier.arrive.expect_tx.shared.b64 _, [%0], %1;" :: "r"(addr), "r"(bytes) : "memory")
#define ST_ASYNC_U32(raddr, val, rmbar) \
    asm volatile("st.async.shared::cluster.mbarrier::complete_tx::bytes.b32 [%0], %1, [%2];" \
                 :: "r"(raddr), "r"(val), "r"(rmbar) : "memory")
#define MBAR_WAIT_CLUSTER(mbar, ph) do {                                              \
    unsigned _done;                                                                   \
    asm volatile("{\n\t.reg .pred p;\n\t"                                             \
        "mbarrier.try_wait.parity.acquire.cluster.shared::cta.b64 p, [%1], %2;\n\t"   \
        "selp.b32 %0, 1, 0, p;\n\t}"                                                  \
        : "=r"(_done) : "r"(mbar), "r"(ph) : "memory");                               \
    while (!_done) {                                                                  \
        asm volatile("{\n\t.reg .pred p;\n\t"                                         \
            "mbarrier.try_wait.parity.acquire.cluster.shared::cta.b64 p, [%1], %2, 0x989680;\n\t" \
            "selp.b32 %0, 1, 0, p;\n\t}"                                              \
            : "=r"(_done) : "r"(mbar), "r"(ph) : "memory");                           \
    }                                                                                 \
} while (0)

// ---------------------------------------------------------------------------
// 2-CTA cluster per batch, 256 threads per CTA, warp-specialized:
//   group X (threads 0..127): owns E for columns rank*128+jl; sends the E
//     half to the peer (st.async), stores it locally, computes part A over
//     the 128 locally-produced states, then after the join does the tail.
//   group Y (threads 128..255): waits on the mbarrier for the peer half,
//     computes part B over the 128 peer states, publishes the partial.
// Part A (X) and [transit + part B] (Y) run CONCURRENTLY; one __syncthreads
// joins them. Lag-1 normalizer rho = rcp(prev step's stored E[0]).
// expect_tx armed one phase ahead (pre-armed in prologue, re-armed by
// thread 128 right after each wait) so arrivals never precede arming.
// ---------------------------------------------------------------------------
__global__ void __launch_bounds__(256, 1) __cluster_dims__(2, 1, 1)
crf_main(const float* __restrict__ emissions,
         const int*   __restrict__ tags,
         const int*   __restrict__ mask,
         const float* __restrict__ trans,
         float*       __restrict__ out)
{
    __shared__ __align__(16) unsigned short sh_e[2][KK];   // full E, 2 stages
    __shared__ float sh_pB[2][HALF];                       // Y's partials
    __shared__ float sh_red[8];
    __shared__ unsigned long long sh_mbar[2];

    const int b    = blockIdx.x >> 1;
    const unsigned rank = ctarank();
    const unsigned peer = rank ^ 1u;
    const int j    = threadIdx.x;            // 0..255
    const int jl   = j & (HALF - 1);         // 0..127
    const int g    = j >> 7;                 // 0 = X, 1 = Y
    const int lane = j & 31;
    const int wid  = j >> 5;
    const int cg   = (int)rank * HALF + jl;  // served output column

    // ---- expT slice for column cg: X gets own-half rows, Y gets peer-half ----
    unsigned int tab[64];
    {
        int base = ((g == 0) ? (int)rank : (int)peer) * HALF;
        #pragma unroll
        for (int w = 0; w < 64; ++w) {
            int i0 = base + 2 * w;
            unsigned lo = f2bf_rn(__expf(trans[i0 * KK + cg]));
            unsigned hi = f2bf_rn(__expf(trans[(i0 + 1) * KK + cg]));
            tab[w] = lo | (hi << 16);
        }
    }

    // ---- joint (numerator) score over all 256 threads ----
    float js = 0.0f;
    #pragma unroll
    for (int h = 0; h < 2; ++h) {
        int t = j + h * 256;
        if (mask[b * TT + t] != 0) {
            int tag = tags[b * TT + t];
            js += emissions[((size_t)b * TT + t) * KK + tag];
            if (t >= 1) js += trans[tags[b * TT + t - 1] * KK + tag];
        }
    }
    #pragma unroll
    for (int s = 16; s; s >>= 1) js += __shfl_xor_sync(0xFFFFFFFFu, js, s);
    if (lane == 0) sh_red[wid] = js;

    // ---- init state (E meaningful for X only) ----
    const float* em_b = emissions + (size_t)b * TT * KK;
    const float nbase = em_b[0];
    float E    = __expf(em_b[cg] - nbase);
    float prod = 1.0f;
    int   cnt  = 0;
    float vcur = 1.0f;                       // lag-1 seed (E_0[0] = 1 exactly)

    __syncthreads();
    float js_tot = 0.0f;
    unsigned mb0 = smem_u32(&sh_mbar[0]), mb1 = smem_u32(&sh_mbar[1]);
    if (j == 0) {
        #pragma unroll
        for (int w = 0; w < 8; ++w) js_tot += sh_red[w];
        MBAR_INIT(mb0, 1);
        MBAR_INIT(mb1, 1);
        // pre-arm BOTH stages (phase 0) before any peer send can exist
        MBAR_EXPECT_TX(mb1, 64 * 4);   // first used at t=1
        MBAR_EXPECT_TX(mb0, 64 * 4);   // first used at t=2
    }
    __syncthreads();
    asm volatile("barrier.cluster.arrive.aligned;" ::: "memory");
    asm volatile("barrier.cluster.wait.aligned;"   ::: "memory");

    // remote addresses (X even threads send packed pair for cols cg, cg+1)
    unsigned ra0 = mapa_u32(smem_u32(&sh_e[0][0]) + (unsigned)cg * 2u, peer);
    unsigned ra1 = mapa_u32(smem_u32(&sh_e[1][0]) + (unsigned)cg * 2u, peer);
    unsigned rm0 = mapa_u32(mb0, peer), rm1 = mapa_u32(mb1, peer);

    int ph0 = 0, ph1 = 0;                    // used by Y only

    float emit = em_b[KK + cg];              // prefetch t=1
    int   mv   = mask[b * TT + 1];

    #define CRF_STEP(T_CUR, BUF)                                               \
    {                                                                          \
        int tn = ((T_CUR) + 1 < TT) ? ((T_CUR) + 1) : (TT - 1);                \
        float emit_n = em_b[tn * KK + cg];                                     \
        int   mv_n   = mask[b * TT + tn];                                      \
        float accA = 0.0f, wr = 0.0f, Erho = 0.0f;                             \
        if (g == 0) {                                                          \
            /* X: normalizer (lag-1), send, local store, part A */             \
            float rho;                                                         \
            asm("rcp.approx.f32 %0, %1;" : "=f"(rho) : "f"(vcur));             \
            wr   = __expf(emit) * rho;                                         \
            Erho = E * rho;                                                    \
            unsigned bits = cvt_bf16(E);                                       \
            unsigned pb   = __shfl_down_sync(0xFFFFFFFFu, bits, 1);            \
            if (!(jl & 1)) {                                                   \
                unsigned pk = bits | (pb << 16);                               \
                ST_ASYNC_U32((BUF) ? ra1 : ra0, pk, (BUF) ? rm1 : rm0);        \
            }                                                                  \
            sh_e[BUF][cg] = (unsigned short)bits;                              \
            asm volatile("bar.sync 1, 128;" ::: "memory");                     \
            const uint4* ebA = (const uint4*)&sh_e[BUF][rank * HALF];          \
            unsigned int c0 = 0u, c1 = 0u;                                     \
            _Pragma("unroll")                                                  \
            for (int q = 0; q < 16; ++q) {                                     \
                uint4 ea = ebA[q];                                             \
                HFMA2_BF16(c0, ea.x, tab[4 * q + 0], c0);                      \
                HFMA2_BF16(c1, ea.y, tab[4 * q + 1], c1);                      \
                HFMA2_BF16(c0, ea.z, tab[4 * q + 2], c0);                      \
                HFMA2_BF16(c1, ea.w, tab[4 * q + 3], c1);                      \
            }                                                                  \
            accA = (__uint_as_float(c0 << 16) + __uint_as_float(c0 & 0xFFFF0000u)) \
                 + (__uint_as_float(c1 << 16) + __uint_as_float(c1 & 0xFFFF0000u)); \
        } else {                                                               \
            /* Y: wait for peer half, re-arm, part B, publish partial */       \
            if (BUF) { MBAR_WAIT_CLUSTER(mb1, ph1); ph1 ^= 1;                  \
                       if (j == 128) MBAR_EXPECT_TX(mb1, 64 * 4); }            \
            else     { MBAR_WAIT_CLUSTER(mb0, ph0); ph0 ^= 1;                  \
                       if (j == 128) MBAR_EXPECT_TX(mb0, 64 * 4); }            \
            const uint4* ebB = (const uint4*)&sh_e[BUF][peer * HALF];          \
            unsigned int c2 = 0u, c3 = 0u;                                     \
            _Pragma("unroll")                                                  \
            for (int q = 0; q < 16; ++q) {                                     \
                uint4 eb = ebB[q];                                             \
                HFMA2_BF16(c2, eb.x, tab[4 * q + 0], c2);                      \
                HFMA2_BF16(c3, eb.y, tab[4 * q + 1], c3);                      \
                HFMA2_BF16(c2, eb.z, tab[4 * q + 2], c2);                      \
                HFMA2_BF16(c3, eb.w, tab[4 * q + 3], c3);                      \
            }                                                                  \
            sh_pB[BUF][jl] =                                                   \
                  (__uint_as_float(c2 << 16) + __uint_as_float(c2 & 0xFFFF0000u)) \
                + (__uint_as_float(c3 << 16) + __uint_as_float(c3 & 0xFFFF0000u)); \
        }                                                                      \
        __syncthreads();                                                       \
        if (g == 0) {                                                          \
            float acc = accA + sh_pB[BUF][jl];                                 \
            E = mv ? (acc * wr) : Erho;                                        \
            /* exchange complete on both ranks here -> E[0] readable */        \
            float vnext = __uint_as_float(((unsigned)sh_e[BUF][0]) << 16);     \
            prod *= vcur;                                                      \
            unsigned up = __float_as_uint(prod);                               \
            cnt += (int)(up >> 23) - 127;                                      \
            prod = __uint_as_float((up & 0x007FFFFFu) | 0x3F800000u);          \
            vcur = vnext;                                                      \
        }                                                                      \
        emit = emit_n; mv = mv_n;                                              \
    }

    // peel t = 1..3, then 127 x 4 steps
    CRF_STEP(1, 1)
    CRF_STEP(2, 0)
    CRF_STEP(3, 1)
    for (int t = 4; t < TT; t += 4) {
        CRF_STEP(t,     0)
        CRF_STEP(t + 1, 1)
        CRF_STEP(t + 2, 0)
        CRF_STEP(t + 3, 1)
    }
    #undef CRF_STEP

    // ---- per-CTA partial sum of E over my 128 columns (X warps only) ----
    float e = (g == 0) ? E : 0.0f;
    #pragma unroll
    for (int s = 16; s; s >>= 1) e += __shfl_xor_sync(0xFFFFFFFFu, e, s);
    if (lane == 0) sh_red[wid] = e;
    __syncthreads();
    if (j == 0) {
        float S = 0.0f;
        #pragma unroll
        for (int w = 0; w < 4; ++w) S += sh_red[w];   // X warps = wid 0..3
        g_pair[b * 2 + (int)rank] = S;
        if (rank == 0) {
            float cf = (float)cnt;
            g_nfin[b] = nbase + cf * 0.693359375f
                      + (cf * -2.1219444e-4f + __logf(prod));
            g_js[b] = js_tot;
        }
        __threadfence();
        unsigned old = atomicAdd(&g_count, 1u);
        if (old == 2u * BB - 1u) {
            g_count = 0;                  // reset for graph replays
            __threadfence();
            float ssum = 0.0f;
            #pragma unroll
            for (int x = 0; x < BB; ++x)
                ssum += g_nfin[x] + __logf(g_pair[2 * x] + g_pair[2 * x + 1]) - g_js[x];
            out[0] = ssum * (1.0f / (float)BB);
        }
    }

    // keep SMEM alive until peer consumed its final incoming writes
    asm volatile("barrier.cluster.arrive.aligned;" ::: "memory");
    asm volatile("barrier.cluster.wait.aligned;"   ::: "memory");
}

extern "C" void kernel_launch(void* const* d_in, const int* in_sizes, int n_in,
                              void* d_out, int out_size) {
    (void)in_sizes; (void)n_in; (void)out_size;
    const float* emissions = (const float*)d_in[0];
    const int*   tags      = (const int*)d_in[1];
    const int*   mask      = (const int*)d_in[2];
    const float* trans     = (const float*)d_in[3];

    crf_main<<<BB * 2, 256>>>(emissions, tags, mask, trans, (float*)d_out);
}

// round 15
// speedup vs baseline: 1.1813x; 1.1813x over previous
#include <cuda_runtime.h>
#include <cuda_bf16.h>
#include <cstdint>

#define BB 32
#define TT 512
#define KK 256
#define HALF 128

__device__ float g_pair[BB * 2];   // per-(batch, rank) partial sums of E
__device__ float g_nfin[BB];       // replicated normalizer (rank 0 writes)
__device__ float g_js[BB];         // joint score (rank 0 writes)
__device__ unsigned int g_count;   // zero-init; reset every launch

static __device__ __forceinline__ unsigned int f2bf_rn(float x) {
    unsigned int u = __float_as_uint(x);
    return (u + 0x7FFFu + ((u >> 16) & 1u)) >> 16;
}
static __device__ __forceinline__ unsigned int cvt_bf16(float x) {
    unsigned short h;
    asm("cvt.rn.bf16.f32 %0, %1;" : "=h"(h) : "f"(x));
    return (unsigned int)h;
}

#define HFMA2_BF16(d, a, b, c) \
    asm("fma.rn.bf16x2 %0, %1, %2, %3;" : "=r"(d) : "r"(a), "r"(b), "r"(c))

static __device__ __forceinline__ unsigned smem_u32(const void* p) {
    return (unsigned)__cvta_generic_to_shared(p);
}
static __device__ __forceinline__ unsigned mapa_u32(unsigned a, unsigned r) {
    unsigned d;
    asm("mapa.shared::cluster.u32 %0, %1, %2;" : "=r"(d) : "r"(a), "r"(r));
    return d;
}
static __device__ __forceinline__ unsigned ctarank() {
    unsigned r; asm("mov.u32 %0, %%cluster_ctarank;" : "=r"(r)); return r;
}

#define MBAR_INIT(addr, cnt) \
    asm volatile("mbarrier.init.shared.b64 [%0], %1;" :: "r"(addr), "r"(cnt) : "memory")
#define MBAR_EXPECT_TX(addr, bytes) \
    asm volatile("mbarrier.arrive.expect_tx.shared.b64 _, [%0], %1;" :: "r"(addr), "r"(bytes) : "memory")
#define ST_ASYNC_U32(raddr, val, rmbar) \
    asm volatile("st.async.shared::cluster.mbarrier::complete_tx::bytes.b32 [%0], %1, [%2];" \
                 :: "r"(raddr), "r"(val), "r"(rmbar) : "memory")
#define MBAR_WAIT_CLUSTER(mbar, ph) do {                                              \
    unsigned _done;                                                                   \
    asm volatile("{\n\t.reg .pred p;\n\t"                                             \
        "mbarrier.try_wait.parity.acquire.cluster.shared::cta.b64 p, [%1], %2;\n\t"   \
        "selp.b32 %0, 1, 0, p;\n\t}"                                                  \
        : "=r"(_done) : "r"(mbar), "r"(ph) : "memory");                               \
    while (!_done) {                                                                  \
        asm volatile("{\n\t.reg .pred p;\n\t"                                         \
            "mbarrier.try_wait.parity.acquire.cluster.shared::cta.b64 p, [%1], %2, 0x989680;\n\t" \
            "selp.b32 %0, 1, 0, p;\n\t}"                                              \
            : "=r"(_done) : "r"(mbar), "r"(ph) : "memory");                           \
    }                                                                                 \
} while (0)

// ---------------------------------------------------------------------------
// 2-CTA cluster per batch; CTA rank r owns output columns r*128..r*128+127,
// full 256-state expT column in 128 bf16x2 registers (own-half tab[0..63],
// peer-half tab[64..127]).
// Per step: rho = rcp(vcur), vcur = previous step's stored E[0] (lag-1,
// register-carried, off the exchange path); st.async my E half to the peer;
// local store; sync; part A (own half); mbarrier wait; part B (peer half);
// minimal tail. Each dot part uses FOUR independent accumulator chains so
// chain-reuse distance (8 cyc) exceeds HFMA2 latency (4) — LDS jitter no
// longer stalls the FMA pipe. expect_tx armed one phase ahead.
// ---------------------------------------------------------------------------
__global__ void __launch_bounds__(128, 1) __cluster_dims__(2, 1, 1)
crf_main(const float* __restrict__ emissions,
         const int*   __restrict__ tags,
         const int*   __restrict__ mask,
         const float* __restrict__ trans,
         float*       __restrict__ out)
{
    __shared__ __align__(16) unsigned short sh_e[2][KK];   // full E, 2 stages
    __shared__ float sh_red[8];
    __shared__ unsigned long long sh_mbar[2];

    const int b    = blockIdx.x >> 1;
    const unsigned rank = ctarank();
    const unsigned peer = rank ^ 1u;
    const int j    = threadIdx.x;           // 0..127
    const int lane = j & 31;
    const int wid  = j >> 5;
    const int cg   = (int)rank * HALF + j;  // my output column

    // ---- expT column cg: own-half states tab[0..63], peer-half tab[64..127] ----
    unsigned int tab[128];
    #pragma unroll
    for (int w = 0; w < 64; ++w) {
        int i0 = (int)rank * HALF + 2 * w;
        unsigned lo = f2bf_rn(__expf(trans[i0 * KK + cg]));
        unsigned hi = f2bf_rn(__expf(trans[(i0 + 1) * KK + cg]));
        tab[w] = lo | (hi << 16);
    }
    #pragma unroll
    for (int w = 0; w < 64; ++w) {
        int i0 = (int)peer * HALF + 2 * w;
        unsigned lo = f2bf_rn(__expf(trans[i0 * KK + cg]));
        unsigned hi = f2bf_rn(__expf(trans[(i0 + 1) * KK + cg]));
        tab[64 + w] = lo | (hi << 16);
    }

    // ---- joint (numerator) score, replicated; rank0 publishes ----
    float js = 0.0f;
    #pragma unroll
    for (int h = 0; h < 4; ++h) {
        int t = j + h * HALF;
        if (mask[b * TT + t] != 0) {
            int tag = tags[b * TT + t];
            js += emissions[((size_t)b * TT + t) * KK + tag];
            if (t >= 1) js += trans[tags[b * TT + t - 1] * KK + tag];
        }
    }
    #pragma unroll
    for (int s = 16; s; s >>= 1) js += __shfl_xor_sync(0xFFFFFFFFu, js, s);
    if (lane == 0) sh_red[wid] = js;

    // ---- init state ----
    const float* em_b = emissions + (size_t)b * TT * KK;
    const float nbase = em_b[0];            // alpha0[0], identical both CTAs
    float E    = __expf(em_b[cg] - nbase);  // E_0 (column 0 thread: exactly 1)
    float prod = 1.0f;
    int   cnt  = 0;
    float vcur = 1.0f;                      // lag-1 normalizer seed (E_0[0] = 1)

    __syncthreads();
    float js_tot = 0.0f;
    unsigned mb0 = smem_u32(&sh_mbar[0]), mb1 = smem_u32(&sh_mbar[1]);
    if (j == 0) {
        #pragma unroll
        for (int w = 0; w < 4; ++w) js_tot += sh_red[w];
        MBAR_INIT(mb0, 1);
        MBAR_INIT(mb1, 1);
        // pre-arm BOTH stages (phase 0) before any peer send exists
        MBAR_EXPECT_TX(mb1, 64 * 4);   // first used at t=1
        MBAR_EXPECT_TX(mb0, 64 * 4);   // first used at t=2
    }
    __syncthreads();
    asm volatile("barrier.cluster.arrive.aligned;" ::: "memory");
    asm volatile("barrier.cluster.wait.aligned;"   ::: "memory");

    // remote addresses (even threads send the packed pair for cols cg, cg+1)
    unsigned ra0 = mapa_u32(smem_u32(&sh_e[0][0]) + (unsigned)cg * 2u, peer);
    unsigned ra1 = mapa_u32(smem_u32(&sh_e[1][0]) + (unsigned)cg * 2u, peer);
    unsigned rm0 = mapa_u32(mb0, peer), rm1 = mapa_u32(mb1, peer);

    int ph0 = 0, ph1 = 0;

    float emit = em_b[KK + cg];             // prefetch t=1
    int   mv   = mask[b * TT + 1];

    #define CRF_STEP(T_CUR, BUF)                                               \
    {                                                                          \
        int tn = ((T_CUR) + 1 < TT) ? ((T_CUR) + 1) : (TT - 1);                \
        float emit_n = em_b[tn * KK + cg];                                     \
        int   mv_n   = mask[b * TT + tn];                                      \
        /* lag-1 normalizer: all off the exchange path */                      \
        float rho;                                                             \
        asm("rcp.approx.f32 %0, %1;" : "=f"(rho) : "f"(vcur));                 \
        float wexp = __expf(emit);                                             \
        float wr   = wexp * rho;                                               \
        float Erho = E * rho;                                                  \
        /* send my E half to peer ASAP (peer's stage already armed) */         \
        unsigned bits = cvt_bf16(E);                                           \
        unsigned pb   = __shfl_down_sync(0xFFFFFFFFu, bits, 1);                \
        if (!(j & 1)) {                                                        \
            unsigned pk = bits | (pb << 16);                                   \
            ST_ASYNC_U32((BUF) ? ra1 : ra0, pk, (BUF) ? rm1 : rm0);            \
        }                                                                      \
        sh_e[BUF][cg] = (unsigned short)bits;                                  \
        __syncthreads();                                                       \
        /* part A: 128 own-half states, FOUR accumulator chains */             \
        const uint4* ebA = (const uint4*)&sh_e[BUF][rank * HALF];              \
        unsigned int a0 = 0u, a1 = 0u, a2 = 0u, a3 = 0u;                       \
        _Pragma("unroll")                                                      \
        for (int q = 0; q < 16; ++q) {                                         \
            uint4 ea = ebA[q];                                                 \
            HFMA2_BF16(a0, ea.x, tab[4 * q + 0], a0);                          \
            HFMA2_BF16(a1, ea.y, tab[4 * q + 1], a1);                          \
            HFMA2_BF16(a2, ea.z, tab[4 * q + 2], a2);                          \
            HFMA2_BF16(a3, ea.w, tab[4 * q + 3], a3);                          \
        }                                                                      \
        float accA = ((__uint_as_float(a0 << 16) + __uint_as_float(a0 & 0xFFFF0000u))  \
                    + (__uint_as_float(a1 << 16) + __uint_as_float(a1 & 0xFFFF0000u))) \
                   + ((__uint_as_float(a2 << 16) + __uint_as_float(a2 & 0xFFFF0000u))  \
                    + (__uint_as_float(a3 << 16) + __uint_as_float(a3 & 0xFFFF0000u))); \
        /* wait for peer half, then re-arm this stage (phase+1) */             \
        if (BUF) { MBAR_WAIT_CLUSTER(mb1, ph1); ph1 ^= 1;                      \
                   if (j == 0) MBAR_EXPECT_TX(mb1, 64 * 4); }                  \
        else     { MBAR_WAIT_CLUSTER(mb0, ph0); ph0 ^= 1;                      \
                   if (j == 0) MBAR_EXPECT_TX(mb0, 64 * 4); }                  \
        /* off-path: this step's stored E[0] for NEXT step's rho */            \
        float vnext = __uint_as_float(((unsigned)sh_e[BUF][0]) << 16);         \
        /* part B: 128 peer-half states, FOUR accumulator chains */            \
        const uint4* ebB = (const uint4*)&sh_e[BUF][peer * HALF];              \
        unsigned int b0r = 0u, b1r = 0u, b2r = 0u, b3r = 0u;                   \
        _Pragma("unroll")                                                      \
        for (int q = 0; q < 16; ++q) {                                         \
            uint4 eb = ebB[q];                                                 \
            HFMA2_BF16(b0r, eb.x, tab[64 + 4 * q + 0], b0r);                   \
            HFMA2_BF16(b1r, eb.y, tab[64 + 4 * q + 1], b1r);                   \
            HFMA2_BF16(b2r, eb.z, tab[64 + 4 * q + 2], b2r);                   \
            HFMA2_BF16(b3r, eb.w, tab[64 + 4 * q + 3], b3r);                   \
        }                                                                      \
        float accB = ((__uint_as_float(b0r << 16) + __uint_as_float(b0r & 0xFFFF0000u))  \
                    + (__uint_as_float(b1r << 16) + __uint_as_float(b1r & 0xFFFF0000u))) \
                   + ((__uint_as_float(b2r << 16) + __uint_as_float(b2r & 0xFFFF0000u))  \
                    + (__uint_as_float(b3r << 16) + __uint_as_float(b3r & 0xFFFF0000u))); \
        float acc = accA + accB;                                               \
        E = mv ? (acc * wr) : Erho;                                            \
        /* replicated normalizer tracking over the v actually used */          \
        prod *= vcur;                                                          \
        unsigned up = __float_as_uint(prod);                                   \
        cnt += (int)(up >> 23) - 127;                                          \
        prod = __uint_as_float((up & 0x007FFFFFu) | 0x3F800000u);              \
        vcur = vnext;                                                          \
        emit = emit_n; mv = mv_n;                                              \
    }

    // peel t = 1..3, then 127 x 4 steps
    CRF_STEP(1, 1)
    CRF_STEP(2, 0)
    CRF_STEP(3, 1)
    for (int t = 4; t < TT; t += 4) {
        CRF_STEP(t,     0)
        CRF_STEP(t + 1, 1)
        CRF_STEP(t + 2, 0)
        CRF_STEP(t + 3, 1)
    }
    #undef CRF_STEP

    // ---- per-CTA partial sum of E over my 128 columns (fixed order) ----
    float e = E;
    #pragma unroll
    for (int s = 16; s; s >>= 1) e += __shfl_xor_sync(0xFFFFFFFFu, e, s);
    if (lane == 0) sh_red[wid] = e;
    __syncthreads();
    if (j == 0) {
        float S = 0.0f;
        #pragma unroll
        for (int w = 0; w < 4; ++w) S += sh_red[w];
        g_pair[b * 2 + (int)rank] = S;
        if (rank == 0) {
            float cf = (float)cnt;
            g_nfin[b] = nbase + cf * 0.693359375f
                      + (cf * -2.1219444e-4f + __logf(prod));
            g_js[b] = js_tot;
        }
        __threadfence();
        unsigned old = atomicAdd(&g_count, 1u);
        if (old == 2u * BB - 1u) {
            g_count = 0;                  // reset for graph replays
            __threadfence();
            float ssum = 0.0f;
            #pragma unroll
            for (int x = 0; x < BB; ++x)
                ssum += g_nfin[x] + __logf(g_pair[2 * x] + g_pair[2 * x + 1]) - g_js[x];
            out[0] = ssum * (1.0f / (float)BB);
        }
    }

    // keep SMEM alive until peer consumed its final incoming writes
    asm volatile("barrier.cluster.arrive.aligned;" ::: "memory");
    asm volatile("barrier.cluster.wait.aligned;"   ::: "memory");
}

extern "C" void kernel_launch(void* const* d_in, const int* in_sizes, int n_in,
                              void* d_out, int out_size) {
    (void)in_sizes; (void)n_in; (void)out_size;
    const float* emissions = (const float*)d_in[0];
    const int*   tags      = (const int*)d_in[1];
    const int*   mask      = (const int*)d_in[2];
    const float* trans     = (const float*)d_in[3];

    crf_main<<<BB * 2, HALF>>>(emissions, tags, mask, trans, (float*)d_out);
}

// round 16
// speedup vs baseline: 1.1924x; 1.0094x over previous
#include <cuda_runtime.h>
#include <cuda_bf16.h>
#include <cstdint>

#define BB 32
#define TT 512
#define KK 256
#define HALF 128

__device__ float g_pair[BB * 2];   // per-(batch, rank) partial sums of E
__device__ float g_nfin[BB];       // replicated normalizer (rank 0 writes)
__device__ float g_js[BB];         // joint score (rank 0 writes)
__device__ unsigned int g_count;   // zero-init; reset every launch

static __device__ __forceinline__ unsigned int f2bf_rn(float x) {
    unsigned int u = __float_as_uint(x);
    return (u + 0x7FFFu + ((u >> 16) & 1u)) >> 16;
}
static __device__ __forceinline__ unsigned int cvt_bf16(float x) {
    unsigned short h;
    asm("cvt.rn.bf16.f32 %0, %1;" : "=h"(h) : "f"(x));
    return (unsigned int)h;
}

#define HFMA2_BF16(d, a, b, c) \
    asm("fma.rn.bf16x2 %0, %1, %2, %3;" : "=r"(d) : "r"(a), "r"(b), "r"(c))
#define HADD2_BF16(d, a, b) \
    asm("add.rn.bf16x2 %0, %1, %2;" : "=r"(d) : "r"(a), "r"(b))

static __device__ __forceinline__ unsigned smem_u32(const void* p) {
    return (unsigned)__cvta_generic_to_shared(p);
}
static __device__ __forceinline__ unsigned mapa_u32(unsigned a, unsigned r) {
    unsigned d;
    asm("mapa.shared::cluster.u32 %0, %1, %2;" : "=r"(d) : "r"(a), "r"(r));
    return d;
}
static __device__ __forceinline__ unsigned ctarank() {
    unsigned r; asm("mov.u32 %0, %%cluster_ctarank;" : "=r"(r)); return r;
}

#define MBAR_INIT(addr, cnt) \
    asm volatile("mbarrier.init.shared.b64 [%0], %1;" :: "r"(addr), "r"(cnt) : "memory")
#define MBAR_EXPECT_TX(addr, bytes) \
    asm volatile("mbarrier.arrive.expect_tx.shared.b64 _, [%0], %1;" :: "r"(addr), "r"(bytes) : "memory")
#define ST_ASYNC_U32(raddr, val, rmbar) \
    asm volatile("st.async.shared::cluster.mbarrier::complete_tx::bytes.b32 [%0], %1, [%2];" \
                 :: "r"(raddr), "r"(val), "r"(rmbar) : "memory")
#define MBAR_WAIT_CLUSTER(mbar, ph) do {                                              \
    unsigned _done;                                                                   \
    asm volatile("{\n\t.reg .pred p;\n\t"                                             \
        "mbarrier.try_wait.parity.acquire.cluster.shared::cta.b64 p, [%1], %2;\n\t"   \
        "selp.b32 %0, 1, 0, p;\n\t}"                                                  \
        : "=r"(_done) : "r"(mbar), "r"(ph) : "memory");                               \
    while (!_done) {                                                                  \
        asm volatile("{\n\t.reg .pred p;\n\t"                                         \
            "mbarrier.try_wait.parity.acquire.cluster.shared::cta.b64 p, [%1], %2, 0x989680;\n\t" \
            "selp.b32 %0, 1, 0, p;\n\t}"                                              \
            : "=r"(_done) : "r"(mbar), "r"(ph) : "memory");                           \
    }                                                                                 \
} while (0)

// ---------------------------------------------------------------------------
// 2-CTA cluster per batch; CTA rank r owns output columns r*128..r*128+127,
// full 256-state expT column in 128 bf16x2 registers (own-half tab[0..63],
// peer-half tab[64..127]).
// Per step: SEND FIRST (cvt E -> st.async to peer; widest transit window),
// then lag-1 normalizer rho = rcp(prev stored E[0]), local store, sync,
// part A (own half, 4 chains), mbarrier wait, part B (peer half, 4 chains),
// minimal tail. Chain combines use add.rn.bf16x2 (3 HADD2 + 1 unpack+FADD
// instead of 15 scalar ops). expect_tx armed one phase ahead.
// ---------------------------------------------------------------------------
__global__ void __launch_bounds__(128, 1) __cluster_dims__(2, 1, 1)
crf_main(const float* __restrict__ emissions,
         const int*   __restrict__ tags,
         const int*   __restrict__ mask,
         const float* __restrict__ trans,
         float*       __restrict__ out)
{
    __shared__ __align__(16) unsigned short sh_e[2][KK];   // full E, 2 stages
    __shared__ float sh_red[8];
    __shared__ unsigned long long sh_mbar[2];

    const int b    = blockIdx.x >> 1;
    const unsigned rank = ctarank();
    const unsigned peer = rank ^ 1u;
    const int j    = threadIdx.x;           // 0..127
    const int lane = j & 31;
    const int wid  = j >> 5;
    const int cg   = (int)rank * HALF + j;  // my output column

    // ---- expT column cg: own-half states tab[0..63], peer-half tab[64..127] ----
    unsigned int tab[128];
    #pragma unroll
    for (int w = 0; w < 64; ++w) {
        int i0 = (int)rank * HALF + 2 * w;
        unsigned lo = f2bf_rn(__expf(trans[i0 * KK + cg]));
        unsigned hi = f2bf_rn(__expf(trans[(i0 + 1) * KK + cg]));
        tab[w] = lo | (hi << 16);
    }
    #pragma unroll
    for (int w = 0; w < 64; ++w) {
        int i0 = (int)peer * HALF + 2 * w;
        unsigned lo = f2bf_rn(__expf(trans[i0 * KK + cg]));
        unsigned hi = f2bf_rn(__expf(trans[(i0 + 1) * KK + cg]));
        tab[64 + w] = lo | (hi << 16);
    }

    // ---- joint (numerator) score, replicated; rank0 publishes ----
    float js = 0.0f;
    #pragma unroll
    for (int h = 0; h < 4; ++h) {
        int t = j + h * HALF;
        if (mask[b * TT + t] != 0) {
            int tag = tags[b * TT + t];
            js += emissions[((size_t)b * TT + t) * KK + tag];
            if (t >= 1) js += trans[tags[b * TT + t - 1] * KK + tag];
        }
    }
    #pragma unroll
    for (int s = 16; s; s >>= 1) js += __shfl_xor_sync(0xFFFFFFFFu, js, s);
    if (lane == 0) sh_red[wid] = js;

    // ---- init state ----
    const float* em_b = emissions + (size_t)b * TT * KK;
    const float nbase = em_b[0];            // alpha0[0], identical both CTAs
    float E    = __expf(em_b[cg] - nbase);  // E_0 (column 0 thread: exactly 1)
    float prod = 1.0f;
    int   cnt  = 0;
    float vcur = 1.0f;                      // lag-1 normalizer seed (E_0[0] = 1)

    __syncthreads();
    float js_tot = 0.0f;
    unsigned mb0 = smem_u32(&sh_mbar[0]), mb1 = smem_u32(&sh_mbar[1]);
    if (j == 0) {
        #pragma unroll
        for (int w = 0; w < 4; ++w) js_tot += sh_red[w];
        MBAR_INIT(mb0, 1);
        MBAR_INIT(mb1, 1);
        // pre-arm BOTH stages (phase 0) before any peer send exists
        MBAR_EXPECT_TX(mb1, 64 * 4);   // first used at t=1
        MBAR_EXPECT_TX(mb0, 64 * 4);   // first used at t=2
    }
    __syncthreads();
    asm volatile("barrier.cluster.arrive.aligned;" ::: "memory");
    asm volatile("barrier.cluster.wait.aligned;"   ::: "memory");

    // remote addresses (even threads send the packed pair for cols cg, cg+1)
    unsigned ra0 = mapa_u32(smem_u32(&sh_e[0][0]) + (unsigned)cg * 2u, peer);
    unsigned ra1 = mapa_u32(smem_u32(&sh_e[1][0]) + (unsigned)cg * 2u, peer);
    unsigned rm0 = mapa_u32(mb0, peer), rm1 = mapa_u32(mb1, peer);

    int ph0 = 0, ph1 = 0;

    float emit = em_b[KK + cg];             // prefetch t=1
    int   mv   = mask[b * TT + 1];

    #define CRF_STEP(T_CUR, BUF)                                               \
    {                                                                          \
        /* SEND FIRST: cvt E, pack pairs, st.async to peer (stage pre-armed) */\
        unsigned bits = cvt_bf16(E);                                           \
        unsigned pb   = __shfl_down_sync(0xFFFFFFFFu, bits, 1);                \
        if (!(j & 1)) {                                                        \
            unsigned pk = bits | (pb << 16);                                   \
            ST_ASYNC_U32((BUF) ? ra1 : ra0, pk, (BUF) ? rm1 : rm0);            \
        }                                                                      \
        sh_e[BUF][cg] = (unsigned short)bits;                                  \
        int tn = ((T_CUR) + 1 < TT) ? ((T_CUR) + 1) : (TT - 1);                \
        float emit_n = em_b[tn * KK + cg];                                     \
        int   mv_n   = mask[b * TT + tn];                                      \
        /* lag-1 normalizer: all off the exchange path */                      \
        float rho;                                                             \
        asm("rcp.approx.f32 %0, %1;" : "=f"(rho) : "f"(vcur));                 \
        float wexp = __expf(emit);                                             \
        float wr   = wexp * rho;                                               \
        float Erho = E * rho;                                                  \
        __syncthreads();                                                       \
        /* part A: 128 own-half states, FOUR chains, HADD2 combine */          \
        const uint4* ebA = (const uint4*)&sh_e[BUF][rank * HALF];              \
        unsigned int a0 = 0u, a1 = 0u, a2 = 0u, a3 = 0u;                       \
        _Pragma("unroll")                                                      \
        for (int q = 0; q < 16; ++q) {                                         \
            uint4 ea = ebA[q];                                                 \
            HFMA2_BF16(a0, ea.x, tab[4 * q + 0], a0);                          \
            HFMA2_BF16(a1, ea.y, tab[4 * q + 1], a1);                          \
            HFMA2_BF16(a2, ea.z, tab[4 * q + 2], a2);                          \
            HFMA2_BF16(a3, ea.w, tab[4 * q + 3], a3);                          \
        }                                                                      \
        unsigned int hA, hA2;                                                  \
        HADD2_BF16(hA, a0, a1);                                                \
        HADD2_BF16(hA2, a2, a3);                                               \
        HADD2_BF16(hA, hA, hA2);                                               \
        float accA = __uint_as_float(hA << 16)                                 \
                   + __uint_as_float(hA & 0xFFFF0000u);                        \
        /* wait for peer half, then re-arm this stage (phase+1) */             \
        if (BUF) { MBAR_WAIT_CLUSTER(mb1, ph1); ph1 ^= 1;                      \
                   if (j == 0) MBAR_EXPECT_TX(mb1, 64 * 4); }                  \
        else     { MBAR_WAIT_CLUSTER(mb0, ph0); ph0 ^= 1;                      \
                   if (j == 0) MBAR_EXPECT_TX(mb0, 64 * 4); }                  \
        /* off-path: this step's stored E[0] for NEXT step's rho */            \
        float vnext = __uint_as_float(((unsigned)sh_e[BUF][0]) << 16);         \
        /* part B: 128 peer-half states, FOUR chains, HADD2 combine */         \
        const uint4* ebB = (const uint4*)&sh_e[BUF][peer * HALF];              \
        unsigned int b0r = 0u, b1r = 0u, b2r = 0u, b3r = 0u;                   \
        _Pragma("unroll")                                                      \
        for (int q = 0; q < 16; ++q) {                                         \
            uint4 eb = ebB[q];                                                 \
            HFMA2_BF16(b0r, eb.x, tab[64 + 4 * q + 0], b0r);                   \
            HFMA2_BF16(b1r, eb.y, tab[64 + 4 * q + 1], b1r);                   \
            HFMA2_BF16(b2r, eb.z, tab[64 + 4 * q + 2], b2r);                   \
            HFMA2_BF16(b3r, eb.w, tab[64 + 4 * q + 3], b3r);                   \
        }                                                                      \
        unsigned int hB, hB2;                                                  \
        HADD2_BF16(hB, b0r, b1r);                                              \
        HADD2_BF16(hB2, b2r, b3r);                                             \
        HADD2_BF16(hB, hB, hB2);                                               \
        float accB = __uint_as_float(hB << 16)                                 \
                   + __uint_as_float(hB & 0xFFFF0000u);                        \
        float acc = accA + accB;                                               \
        E = mv ? (acc * wr) : Erho;                                            \
        /* replicated normalizer tracking over the v actually used */          \
        prod *= vcur;                                                          \
        unsigned up = __float_as_uint(prod);                                   \
        cnt += (int)(up >> 23) - 127;                                          \
        prod = __uint_as_float((up & 0x007FFFFFu) | 0x3F800000u);              \
        vcur = vnext;                                                          \
        emit = emit_n; mv = mv_n;                                              \
    }

    // peel t = 1..3, then 127 x 4 steps
    CRF_STEP(1, 1)
    CRF_STEP(2, 0)
    CRF_STEP(3, 1)
    for (int t = 4; t < TT; t += 4) {
        CRF_STEP(t,     0)
        CRF_STEP(t + 1, 1)
        CRF_STEP(t + 2, 0)
        CRF_STEP(t + 3, 1)
    }
    #undef CRF_STEP

    // ---- per-CTA partial sum of E over my 128 columns (fixed order) ----
    float e = E;
    #pragma unroll
    for (int s = 16; s; s >>= 1) e += __shfl_xor_sync(0xFFFFFFFFu, e, s);
    if (lane == 0) sh_red[wid] = e;
    __syncthreads();
    if (j == 0) {
        float S = 0.0f;
        #pragma unroll
        for (int w = 0; w < 4; ++w) S += sh_red[w];
        g_pair[b * 2 + (int)rank] = S;
        if (rank == 0) {
            float cf = (float)cnt;
            g_nfin[b] = nbase + cf * 0.693359375f
                      + (cf * -2.1219444e-4f + __logf(prod));
            g_js[b] = js_tot;
        }
        __threadfence();
        unsigned old = atomicAdd(&g_count, 1u);
        if (old == 2u * BB - 1u) {
            g_count = 0;                  // reset for graph replays
            __threadfence();
            float ssum = 0.0f;
            #pragma unroll
            for (int x = 0; x < BB; ++x)
                ssum += g_nfin[x] + __logf(g_pair[2 * x] + g_pair[2 * x + 1]) - g_js[x];
            out[0] = ssum * (1.0f / (float)BB);
        }
    }

    // keep SMEM alive until peer consumed its final incoming writes
    asm volatile("barrier.cluster.arrive.aligned;" ::: "memory");
    asm volatile("barrier.cluster.wait.aligned;"   ::: "memory");
}

extern "C" void kernel_launch(void* const* d_in, const int* in_sizes, int n_in,
                              void* d_out, int out_size) {
    (void)in_sizes; (void)n_in; (void)out_size;
    const float* emissions = (const float*)d_in[0];
    const int*   tags      = (const int*)d_in[1];
    const int*   mask      = (const int*)d_in[2];
    const float* trans     = (const float*)d_in[3];

    crf_main<<<BB * 2, HALF>>>(emissions, tags, mask, trans, (float*)d_out);
}